// round 3
// baseline (speedup 1.0000x reference)
#include <cuda_runtime.h>
#include <math.h>
#include <cstdint>

// Problem dims
#define BATCH 16384
#define FF    50
#define EE    64
#define FE    3200      // F*E
#define DD    512
#define NPAIR 1275      // F*(F+1)/2
#define KPAD  1280      // NPAIR padded to mult of 32
#define HH1   1024
#define HH2   512

// ---------------- scratch (device globals; no allocation allowed) ----------
__device__ float g_emb [(size_t)BATCH * FE];
__device__ float g_gram[(size_t)BATCH * KPAD];
__device__ float g_PL  [(size_t)DD * FE];
__device__ float g_R   [(size_t)DD * KPAD];
__device__ float g_W0t [(size_t)HH1 * DD];
__device__ float g_W1t [(size_t)HH2 * HH1];
__device__ float g_lz  [(size_t)BATCH * DD];
__device__ float g_y0  [(size_t)BATCH * DD];
__device__ float g_y1  [(size_t)BATCH * HH1];
__device__ float g_y2  [(size_t)BATCH * HH2];
__device__ float g_pS  [128 * HH1];
__device__ float g_pQ  [128 * HH1];
__device__ float g_bnA1[HH1], g_bnB1[HH1];
__device__ float g_bnA2[HH2], g_bnB2[HH2];

// ---------------- helpers ---------------------------------------------------
__device__ __forceinline__ float tf32r(float x) {
    unsigned u;
    asm("cvt.rna.tf32.f32 %0, %1;" : "=r"(u) : "f"(x));
    return __uint_as_float(u);
}

__device__ __forceinline__ void mma8(float d[4], const uint32_t a[4], const uint32_t b[2]) {
    asm volatile(
        "mma.sync.aligned.m16n8k8.row.col.f32.tf32.tf32.f32 "
        "{%0,%1,%2,%3}, {%4,%5,%6,%7}, {%8,%9}, {%0,%1,%2,%3};"
        : "+f"(d[0]), "+f"(d[1]), "+f"(d[2]), "+f"(d[3])
        : "r"(a[0]), "r"(a[1]), "r"(a[2]), "r"(a[3]), "r"(b[0]), "r"(b[1]));
}

// p -> (f1,f2), f1<=f2, row-major upper triangle
__device__ __forceinline__ void pair_of(int p, int& f1, int& f2) {
    int a = 0, rem = p;
    while (rem >= FF - a) { rem -= FF - a; a++; }
    f1 = a; f2 = a + rem;
}

// ---------------- K1: embedding gather (tf32-rounded) ----------------------
__global__ void embed_kernel(const int* __restrict__ fidx,
                             const float* __restrict__ fval,
                             const float* __restrict__ femb) {
    int t = threadIdx.x;
    int e = t & 63;
    int row = blockIdx.x * 4 + (t >> 6);
    int i = fidx[row];
    float v = fval[row];
    g_emb[(size_t)row * EE + e] = tf32r(femb[(size_t)i * EE + e] * v);
}

// ---------------- K2: Gram G[b,p] = <emb_b[f1,:], emb_b[f2,:]> -------------
// 4x4 register tiles over (f1,f2) blocks; 2 batch rows per CTA.
__global__ __launch_bounds__(256)
void gram_kernel() {
    __shared__ float es[2][52 * 72];
    int h = threadIdx.x >> 7, t = threadIdx.x & 127;
    int b = blockIdx.x * 2 + h;
    float* E = es[h];
    for (int idx = t; idx < 52 * 72; idx += 128) E[idx] = 0.f;
    __syncthreads();
    const float* src = g_emb + (size_t)b * FE;
    for (int idx = t; idx < FE; idx += 128)
        E[(idx >> 6) * 72 + (idx & 63)] = src[idx];
    __syncthreads();

    float* dst = g_gram + (size_t)b * KPAD;
    if (t < 91) {
        int I = 0, rem = t;
        while (rem >= 13 - I) { rem -= 13 - I; I++; }
        int J = I + rem;
        float acc[4][4] = {};
        const float* r1 = E + 4 * I * 72;
        const float* r2 = E + 4 * J * 72;
        for (int k = 0; k < 64; k += 4) {
            float4 x[4], y[4];
            #pragma unroll
            for (int a = 0; a < 4; a++) x[a] = *(const float4*)(r1 + a * 72 + k);
            #pragma unroll
            for (int a = 0; a < 4; a++) y[a] = *(const float4*)(r2 + a * 72 + k);
            #pragma unroll
            for (int a = 0; a < 4; a++)
                #pragma unroll
                for (int c = 0; c < 4; c++)
                    acc[a][c] += x[a].x * y[c].x + x[a].y * y[c].y +
                                 x[a].z * y[c].z + x[a].w * y[c].w;
        }
        #pragma unroll
        for (int a = 0; a < 4; a++) {
            int f1 = 4 * I + a;
            #pragma unroll
            for (int c = 0; c < 4; c++) {
                int f2 = 4 * J + c;
                if (f1 <= f2 && f2 < FF) {
                    int p = f1 * FF - (f1 * (f1 - 1)) / 2 + (f2 - f1);
                    dst[p] = tf32r(acc[a][c]);
                }
            }
        }
    } else if (t == 91) {
        #pragma unroll
        for (int q = 0; q < 5; q++) dst[NPAIR + q] = 0.f;
    }
}

// ---------------- K3: R[d,p] = q[d,f1]*q[d,f2]*(f1==f2?1:2) ----------------
__global__ void rk_kernel(const float* __restrict__ q) {
    int d = blockIdx.x;
    const float* qd = q + d * FF;
    float* dst = g_R + (size_t)d * KPAD;
    for (int p = threadIdx.x; p < KPAD; p += 256) {
        float v = 0.f;
        if (p < NPAIR) {
            int f1, f2; pair_of(p, f1, f2);
            v = tf32r(qd[f1] * qd[f2] * ((f1 == f2) ? 1.f : 2.f));
        }
        dst[p] = v;
    }
}

// ---------------- K4: rounded copy of product_linear -----------------------
__global__ void plcopy_kernel(const float* __restrict__ pl) {
    size_t i = (size_t)blockIdx.x * 1024 + threadIdx.x;
    if (i < (size_t)DD * FE) g_PL[i] = tf32r(pl[i]);
}

// ---------------- K5: weight transpose (to K-major), rounded ---------------
__global__ void transpose_kernel(const float* __restrict__ W, float* __restrict__ Wt,
                                 int R, int Cc) {
    __shared__ float tile[32][33];
    int c0 = blockIdx.x * 32, r0 = blockIdx.y * 32;
    int x = threadIdx.x, y = threadIdx.y;      // 32 x 8
    #pragma unroll
    for (int i = 0; i < 32; i += 8)
        tile[y + i][x] = W[(size_t)(r0 + y + i) * Cc + c0 + x];
    __syncthreads();
    #pragma unroll
    for (int i = 0; i < 32; i += 8)
        Wt[(size_t)(c0 + y + i) * R + r0 + x] = tf32r(tile[x][y + i]);
}

// ---------------- tensor-core GEMM via mma.sync tf32 -----------------------
// C(16384 x Ntot) = A(16384 x K, row-major) @ B(Ntot x K, K-major)^T
// CTA tile 128x128, BK=32, 8 warps of 64x32, double-buffered fragment-packed SMEM.
// EPI 0: plain store. EPI 1: C = tf32r(relu(lz + sqrt(max(acc,0)) + pbias)).
// EPI 2: C = acc + bias; emit per-Mtile column partial sum/sumsq.
// ABN  : on A load, a = tf32r(relu(a*aA[k] + aB[k])).
template<int EPI, bool ABN>
__global__ __launch_bounds__(256)
void mma_gemm(const float* __restrict__ A, const float* __restrict__ B,
              float* __restrict__ C, int Ntot, int K,
              const float* __restrict__ aA, const float* __restrict__ aB,
              const float* __restrict__ bias,
              const float* __restrict__ lzp, const float* __restrict__ pbias,
              float* __restrict__ statS, float* __restrict__ statQ) {
    extern __shared__ float sm[];   // [A0 4096][B0 4096][A1 4096][B1 4096]
    const int tid = threadIdx.x;
    const int l = tid & 31, w = tid >> 5;
    const int wm = w >> 2, wn = w & 3;
    const int m0 = blockIdx.y * 128, n0 = blockIdx.x * 128;
    const int NC = K >> 5;

    // staging map: thread -> (m,k0) / (n,k0), bank-conflict-free STS via rotation
    const int k0  = (l & 7) * 4;
    const int ksC = k0 >> 3;
    const int kb2 = (k0 >> 2) & 1;
    const int rot = (l >> 1) & 3;
    const int mb  = ((l >> 3) & 1) + 8 * ((l >> 4) & 1) + 2 * (w & 3) + 16 * (w >> 2);
    const int nb  = (l >> 3) + 4 * w;
    const int aLow = (mb & 7) * 16 + ((mb >> 3) & 1) + 2 * kb2;  // +4*j
    const int aC1  = mb >> 4;
    const int bLow = (nb & 7) * 8 + kb2;                          // +2*j
    const int bC1  = nb >> 3;

    const float* Aptr = A + (size_t)m0 * K;
    const float* Bptr = B + (size_t)n0 * K;

    float4 va[4], vb[4];
    #pragma unroll
    for (int i = 0; i < 4; i++)
        va[i] = *(const float4*)(Aptr + (size_t)(mb + 32 * i) * K + k0);
    if (ABN) {
        #pragma unroll
        for (int i = 0; i < 4; i++) {
            float4 v = va[i];
            v.x = tf32r(fmaxf(0.f, fmaf(v.x, aA[k0 + 0], aB[k0 + 0])));
            v.y = tf32r(fmaxf(0.f, fmaf(v.y, aA[k0 + 1], aB[k0 + 1])));
            v.z = tf32r(fmaxf(0.f, fmaf(v.z, aA[k0 + 2], aB[k0 + 2])));
            v.w = tf32r(fmaxf(0.f, fmaf(v.w, aA[k0 + 3], aB[k0 + 3])));
            va[i] = v;
        }
    }
    #pragma unroll
    for (int i = 0; i < 4; i++)
        vb[i] = *(const float4*)(Bptr + (size_t)(nb + 32 * i) * K + k0);

    // STS of a staged tile into buffer at float offsets (ao, bo)
    #define STS_TILE(ao, bo)                                                     \
        do {                                                                     \
            _Pragma("unroll")                                                    \
            for (int i = 0; i < 4; i++) {                                        \
                int wbase = (ao) + ((aC1 + 2 * i) * 4 + ksC) * 128 + aLow;       \
                float4 v = va[i];                                                \
                _Pragma("unroll")                                                \
                for (int s = 0; s < 4; s++) {                                    \
                    int j = (s + rot) & 3;                                       \
                    float x = (j == 0) ? v.x : (j == 1) ? v.y : (j == 2) ? v.z : v.w; \
                    sm[wbase + 4 * j] = x;                                       \
                }                                                                \
            }                                                                    \
            _Pragma("unroll")                                                    \
            for (int i = 0; i < 4; i++) {                                        \
                int wbase = (bo) + ((bC1 + 4 * i) * 4 + ksC) * 64 + bLow;        \
                float4 v = vb[i];                                                \
                _Pragma("unroll")                                                \
                for (int s = 0; s < 4; s++) {                                    \
                    int j = (s + rot) & 3;                                       \
                    float x = (j == 0) ? v.x : (j == 1) ? v.y : (j == 2) ? v.z : v.w; \
                    sm[wbase + 2 * j] = x;                                       \
                }                                                                \
            }                                                                    \
        } while (0)

    STS_TILE(0, 4096);
    __syncthreads();

    float acc[4][4][4];
    #pragma unroll
    for (int i = 0; i < 4; i++)
        #pragma unroll
        for (int j = 0; j < 4; j++)
            #pragma unroll
            for (int r = 0; r < 4; r++) acc[i][j][r] = 0.f;

    for (int c = 0; c < NC; c++) {
        const int Ab = (c & 1) * 8192, Bb = Ab + 4096;
        const bool more = (c + 1 < NC);
        if (more) {
            int kb = (c + 1) * 32;
            #pragma unroll
            for (int i = 0; i < 4; i++)
                va[i] = *(const float4*)(Aptr + (size_t)(mb + 32 * i) * K + kb + k0);
            if (ABN) {
                #pragma unroll
                for (int i = 0; i < 4; i++) {
                    float4 v = va[i];
                    int kg = kb + k0;
                    v.x = tf32r(fmaxf(0.f, fmaf(v.x, aA[kg + 0], aB[kg + 0])));
                    v.y = tf32r(fmaxf(0.f, fmaf(v.y, aA[kg + 1], aB[kg + 1])));
                    v.z = tf32r(fmaxf(0.f, fmaf(v.z, aA[kg + 2], aB[kg + 2])));
                    v.w = tf32r(fmaxf(0.f, fmaf(v.w, aA[kg + 3], aB[kg + 3])));
                    va[i] = v;
                }
            }
            #pragma unroll
            for (int i = 0; i < 4; i++)
                vb[i] = *(const float4*)(Bptr + (size_t)(nb + 32 * i) * K + kb + k0);
        }
        #pragma unroll
        for (int ks = 0; ks < 4; ks++) {
            uint32_t af[4][4], bf[4][2];
            #pragma unroll
            for (int i = 0; i < 4; i++) {
                const float4 t4 = *(const float4*)(&sm[Ab + (((wm * 4 + i) * 4 + ks) * 32 + l) * 4]);
                af[i][0] = __float_as_uint(t4.x); af[i][1] = __float_as_uint(t4.y);
                af[i][2] = __float_as_uint(t4.z); af[i][3] = __float_as_uint(t4.w);
            }
            #pragma unroll
            for (int jn = 0; jn < 4; jn++) {
                const float2 t2 = *(const float2*)(&sm[Bb + (((wn * 4 + jn) * 4 + ks) * 32 + l) * 2]);
                bf[jn][0] = __float_as_uint(t2.x); bf[jn][1] = __float_as_uint(t2.y);
            }
            #pragma unroll
            for (int i = 0; i < 4; i++)
                #pragma unroll
                for (int jn = 0; jn < 4; jn++)
                    mma8(acc[i][jn], af[i], bf[jn]);
        }
        if (more) {
            const int An = ((c + 1) & 1) * 8192;
            STS_TILE(An, An + 4096);
            __syncthreads();
        }
    }

    // ---- epilogue ----
    const int r0 = m0 + wm * 64 + (l >> 2);
    const int c0b = n0 + wn * 32 + (l & 3) * 2;
    float sS[4][2] = {}, sQ[4][2] = {};
    #pragma unroll
    for (int i = 0; i < 4; i++) {
        int r = r0 + i * 16;
        #pragma unroll
        for (int jn = 0; jn < 4; jn++) {
            int cc = c0b + jn * 8;
            float d0 = acc[i][jn][0], d1 = acc[i][jn][1];
            float d2 = acc[i][jn][2], d3 = acc[i][jn][3];
            if (EPI == 1) {
                d0 = tf32r(fmaxf(0.f, lzp[(size_t)r * Ntot + cc]           + sqrtf(fmaxf(d0, 0.f)) + pbias[cc]));
                d1 = tf32r(fmaxf(0.f, lzp[(size_t)r * Ntot + cc + 1]       + sqrtf(fmaxf(d1, 0.f)) + pbias[cc + 1]));
                d2 = tf32r(fmaxf(0.f, lzp[(size_t)(r + 8) * Ntot + cc]     + sqrtf(fmaxf(d2, 0.f)) + pbias[cc]));
                d3 = tf32r(fmaxf(0.f, lzp[(size_t)(r + 8) * Ntot + cc + 1] + sqrtf(fmaxf(d3, 0.f)) + pbias[cc + 1]));
            } else if (EPI == 2) {
                float b0v = bias[cc], b1v = bias[cc + 1];
                d0 += b0v; d1 += b1v; d2 += b0v; d3 += b1v;
                sS[jn][0] += d0 + d2;         sS[jn][1] += d1 + d3;
                sQ[jn][0] += d0 * d0 + d2 * d2; sQ[jn][1] += d1 * d1 + d3 * d3;
            }
            *(float2*)(C + (size_t)r * Ntot + cc)       = make_float2(d0, d1);
            *(float2*)(C + (size_t)(r + 8) * Ntot + cc) = make_float2(d2, d3);
        }
    }
    if (EPI == 2) {
        #pragma unroll
        for (int jn = 0; jn < 4; jn++)
            #pragma unroll
            for (int e = 0; e < 2; e++) {
                #pragma unroll
                for (int off = 4; off < 32; off <<= 1) {
                    sS[jn][e] += __shfl_xor_sync(0xffffffffu, sS[jn][e], off);
                    sQ[jn][e] += __shfl_xor_sync(0xffffffffu, sQ[jn][e], off);
                }
            }
        __syncthreads();
        if ((l >> 2) == 0) {
            #pragma unroll
            for (int jn = 0; jn < 4; jn++)
                #pragma unroll
                for (int e = 0; e < 2; e++) {
                    int cl = wn * 32 + jn * 8 + (l & 3) * 2 + e;
                    sm[wm * 128 + cl]       = sS[jn][e];
                    sm[256 + wm * 128 + cl] = sQ[jn][e];
                }
        }
        __syncthreads();
        if (tid < 128) {
            statS[(size_t)blockIdx.y * Ntot + n0 + tid] = sm[tid] + sm[128 + tid];
            statQ[(size_t)blockIdx.y * Ntot + n0 + tid] = sm[256 + tid] + sm[384 + tid];
        }
    }
    #undef STS_TILE
}

// ---------------- BN finalize ----------------------------------------------
__global__ void bnfin_kernel(const float* __restrict__ pS,
                             const float* __restrict__ pQ, int H,
                             const float* __restrict__ scale,
                             const float* __restrict__ offset,
                             float* __restrict__ oA, float* __restrict__ oB) {
    int c = blockIdx.x * blockDim.x + threadIdx.x;
    if (c >= H) return;
    float s = 0.f, q = 0.f;
    for (int t = 0; t < 128; t++) { s += pS[t * H + c]; q += pQ[t * H + c]; }
    float m = s * (1.f / (float)BATCH);
    float v = q * (1.f / (float)BATCH) - m * m;
    float a = scale[0] * rsqrtf(fmaxf(v, 0.f) + 1e-10f);
    oA[c] = a;
    oB[c] = offset[0] - m * a;
}

// ---------------- output head ----------------------------------------------
__global__ void out_kernel(const float* __restrict__ w,
                           const float* __restrict__ ob,
                           float* __restrict__ out) {
    int b = blockIdx.x;
    int tid = threadIdx.x;   // 128 threads
    const float* row = g_y2 + (size_t)b * HH2;
    float s = 0.f;
    #pragma unroll
    for (int n = tid; n < HH2; n += 128) {
        float v = fmaxf(0.f, row[n] * g_bnA2[n] + g_bnB2[n]);
        s += v * w[n];
    }
    __shared__ float red[128];
    red[tid] = s;
    __syncthreads();
    for (int off = 64; off > 0; off >>= 1) {
        if (tid < off) red[tid] += red[tid + off];
        __syncthreads();
    }
    if (tid == 0) {
        float x = red[0] + ob[0];
        out[b] = 1.f / (1.f + expf(-x));
    }
}

// ---------------- launch ----------------------------------------------------
extern "C" void kernel_launch(void* const* d_in, const int* in_sizes, int n_in,
                              void* d_out, int out_size) {
    const int*   fidx  = (const int*)  d_in[0];
    const float* fval  = (const float*)d_in[1];
    const float* femb  = (const float*)d_in[2];
    const float* pl    = (const float*)d_in[3];
    const float* pbias = (const float*)d_in[4];
    const float* pq    = (const float*)d_in[5];
    const float* W0    = (const float*)d_in[6];
    const float* b0    = (const float*)d_in[7];
    const float* W1    = (const float*)d_in[8];
    const float* b1    = (const float*)d_in[9];
    const float* bnS   = (const float*)d_in[10];
    const float* bnO   = (const float*)d_in[11];
    const float* ow    = (const float*)d_in[12];
    const float* ob    = (const float*)d_in[13];
    float* out = (float*)d_out;

    void *emb, *gram, *PL, *R, *W0t, *W1t, *lz, *y0, *y1, *y2, *pS, *pQ;
    void *A1, *B1, *A2, *B2;
    cudaGetSymbolAddress(&emb,  g_emb);
    cudaGetSymbolAddress(&gram, g_gram);
    cudaGetSymbolAddress(&PL,   g_PL);
    cudaGetSymbolAddress(&R,    g_R);
    cudaGetSymbolAddress(&W0t,  g_W0t);
    cudaGetSymbolAddress(&W1t,  g_W1t);
    cudaGetSymbolAddress(&lz,   g_lz);
    cudaGetSymbolAddress(&y0,   g_y0);
    cudaGetSymbolAddress(&y1,   g_y1);
    cudaGetSymbolAddress(&y2,   g_y2);
    cudaGetSymbolAddress(&pS,   g_pS);
    cudaGetSymbolAddress(&pQ,   g_pQ);
    cudaGetSymbolAddress(&A1,   g_bnA1);
    cudaGetSymbolAddress(&B1,   g_bnB1);
    cudaGetSymbolAddress(&A2,   g_bnA2);
    cudaGetSymbolAddress(&B2,   g_bnB2);

    const int SMEM = 16384 * 4;   // 64 KB
    cudaFuncSetAttribute(mma_gemm<0, false>, cudaFuncAttributeMaxDynamicSharedMemorySize, SMEM);
    cudaFuncSetAttribute(mma_gemm<1, false>, cudaFuncAttributeMaxDynamicSharedMemorySize, SMEM);
    cudaFuncSetAttribute(mma_gemm<2, false>, cudaFuncAttributeMaxDynamicSharedMemorySize, SMEM);
    cudaFuncSetAttribute(mma_gemm<2, true >, cudaFuncAttributeMaxDynamicSharedMemorySize, SMEM);

    // prep
    embed_kernel<<<(BATCH * FF) / 4, 256>>>(fidx, fval, femb);
    gram_kernel<<<BATCH / 2, 256>>>();
    rk_kernel<<<DD, 256>>>(pq);
    plcopy_kernel<<<(DD * FE + 1023) / 1024, 1024>>>(pl);
    transpose_kernel<<<dim3(HH1 / 32, DD / 32), dim3(32, 8)>>>(W0, (float*)W0t, DD, HH1);
    transpose_kernel<<<dim3(HH2 / 32, HH1 / 32), dim3(32, 8)>>>(W1, (float*)W1t, HH1, HH2);

    // LZ = emb @ PL^T  (N=512, K=3200)
    mma_gemm<0, false><<<dim3(4, 128), 256, SMEM>>>(
        (const float*)emb, (const float*)PL, (float*)lz, DD, FE,
        nullptr, nullptr, nullptr, nullptr, nullptr, nullptr, nullptr);
    // y0 = relu(lz + sqrt(G @ R^T) + pbias)  (N=512, K=1280)
    mma_gemm<1, false><<<dim3(4, 128), 256, SMEM>>>(
        (const float*)gram, (const float*)R, (float*)y0, DD, KPAD,
        nullptr, nullptr, nullptr, (const float*)lz, pbias, nullptr, nullptr);
    // y1 = y0 @ W0 + b0  (N=1024, K=512) + BN partials
    mma_gemm<2, false><<<dim3(8, 128), 256, SMEM>>>(
        (const float*)y0, (const float*)W0t, (float*)y1, HH1, DD,
        nullptr, nullptr, b0, nullptr, nullptr, (float*)pS, (float*)pQ);
    bnfin_kernel<<<HH1 / 256, 256>>>((const float*)pS, (const float*)pQ, HH1,
                                     bnS, bnO, (float*)A1, (float*)B1);
    // y2 = bnrelu(y1) @ W1 + b1  (N=512, K=1024) + BN partials
    mma_gemm<2, true><<<dim3(4, 128), 256, SMEM>>>(
        (const float*)y1, (const float*)W1t, (float*)y2, HH2, HH1,
        (const float*)A1, (const float*)B1, b1, nullptr, nullptr,
        (float*)pS, (float*)pQ);
    bnfin_kernel<<<HH2 / 256, 256>>>((const float*)pS, (const float*)pQ, HH2,
                                     bnS, bnO, (float*)A2, (float*)B2);
    // head
    out_kernel<<<BATCH, 128>>>(ow, ob, out);
}

// round 4
// speedup vs baseline: 2.5581x; 2.5581x over previous
#include <cuda_runtime.h>
#include <cuda_fp16.h>
#include <math.h>
#include <cstdint>

// Problem dims
#define BATCH 16384
#define FF    50
#define EE    64
#define FE    3200      // F*E
#define DD    512
#define NPAIR 1275      // F*(F+1)/2
#define KPAD  1280      // NPAIR padded to mult of 32
#define HH1   1024
#define HH2   512

// ---------------- scratch (device globals; no allocation allowed) ----------
__device__ __half g_emb [(size_t)BATCH * FE];
__device__ __half g_gram[(size_t)BATCH * KPAD];
__device__ __half g_PL  [(size_t)DD * FE];
__device__ __half g_R   [(size_t)DD * KPAD];
__device__ __half g_W0t [(size_t)HH1 * DD];
__device__ __half g_W1t [(size_t)HH2 * HH1];
__device__ __half g_y0h [(size_t)BATCH * DD];
__device__ __half g_y1h [(size_t)BATCH * HH1];
__device__ __half g_y2h [(size_t)BATCH * HH2];
__device__ float  g_lz  [(size_t)BATCH * DD];
__device__ float  g_pS  [128 * HH1];
__device__ float  g_pQ  [128 * HH1];
__device__ float  g_bnA1[HH1], g_bnB1[HH1];
__device__ float  g_bnA2[HH2], g_bnB2[HH2];

// ---------------- helpers ---------------------------------------------------
__device__ __forceinline__ uint32_t smem_u32(const void* p) {
    uint32_t a;
    asm("{ .reg .u64 t; cvta.to.shared.u64 t, %1; cvt.u32.u64 %0, t; }"
        : "=r"(a) : "l"(p));
    return a;
}

__device__ __forceinline__ void ldsm_x4(uint32_t r[4], uint32_t addr) {
    asm volatile("ldmatrix.sync.aligned.m8n8.x4.shared.b16 {%0,%1,%2,%3}, [%4];"
        : "=r"(r[0]), "=r"(r[1]), "=r"(r[2]), "=r"(r[3]) : "r"(addr));
}

__device__ __forceinline__ void mma16(float d[4], const uint32_t a[4], const uint32_t b[2]) {
    asm volatile(
        "mma.sync.aligned.m16n8k16.row.col.f32.f16.f16.f32 "
        "{%0,%1,%2,%3}, {%4,%5,%6,%7}, {%8,%9}, {%0,%1,%2,%3};"
        : "+f"(d[0]), "+f"(d[1]), "+f"(d[2]), "+f"(d[3])
        : "r"(a[0]), "r"(a[1]), "r"(a[2]), "r"(a[3]), "r"(b[0]), "r"(b[1]));
}

// BN+relu on a packed half2 word, k index kg (fp32 math, back to half)
__device__ __forceinline__ uint32_t bnpair(uint32_t w, const float* __restrict__ aA,
                                           const float* __restrict__ aB, int kg) {
    __half2 h = *reinterpret_cast<__half2*>(&w);
    float x = __low2float(h), y = __high2float(h);
    x = fmaxf(0.f, fmaf(x, aA[kg], aB[kg]));
    y = fmaxf(0.f, fmaf(y, aA[kg + 1], aB[kg + 1]));
    __half2 r = __floats2half2_rn(x, y);
    return *reinterpret_cast<uint32_t*>(&r);
}

// p -> (f1,f2), f1<=f2
__device__ __forceinline__ void pair_of(int p, int& f1, int& f2) {
    int a = 0, rem = p;
    while (rem >= FF - a) { rem -= FF - a; a++; }
    f1 = a; f2 = a + rem;
}

// SW128 tile offset: tile stored as 64 rows x 128B; element (row r0..63, cc 16B-col 0..7)
__device__ __forceinline__ int swz_off(int r, int cc) {
    return r * 128 + 16 * (cc ^ (r & 7));
}

// ---------------- K1: embedding gather --------------------------------------
__global__ void embed_kernel(const int* __restrict__ fidx,
                             const float* __restrict__ fval,
                             const float* __restrict__ femb) {
    int t = threadIdx.x;
    int e = t & 63;
    int row = blockIdx.x * 4 + (t >> 6);
    int i = fidx[row];
    float v = fval[row];
    g_emb[(size_t)row * EE + e] = __float2half(femb[(size_t)i * EE + e] * v);
}

// ---------------- K2: Gram G[b,p] (fp32 math, half out) --------------------
__global__ __launch_bounds__(256)
void gram_kernel() {
    __shared__ float es[2][52 * 72];
    int h = threadIdx.x >> 7, t = threadIdx.x & 127;
    int b = blockIdx.x * 2 + h;
    float* E = es[h];
    for (int idx = t; idx < 52 * 72; idx += 128) E[idx] = 0.f;
    __syncthreads();
    const __half* src = g_emb + (size_t)b * FE;
    for (int idx = t; idx < FE; idx += 128)
        E[(idx >> 6) * 72 + (idx & 63)] = __half2float(src[idx]);
    __syncthreads();

    __half* dst = g_gram + (size_t)b * KPAD;
    if (t < 91) {
        int I = 0, rem = t;
        while (rem >= 13 - I) { rem -= 13 - I; I++; }
        int J = I + rem;
        float acc[4][4] = {};
        const float* r1 = E + 4 * I * 72;
        const float* r2 = E + 4 * J * 72;
        for (int k = 0; k < 64; k += 4) {
            float4 x[4], y[4];
            #pragma unroll
            for (int a = 0; a < 4; a++) x[a] = *(const float4*)(r1 + a * 72 + k);
            #pragma unroll
            for (int a = 0; a < 4; a++) y[a] = *(const float4*)(r2 + a * 72 + k);
            #pragma unroll
            for (int a = 0; a < 4; a++)
                #pragma unroll
                for (int c = 0; c < 4; c++)
                    acc[a][c] += x[a].x * y[c].x + x[a].y * y[c].y +
                                 x[a].z * y[c].z + x[a].w * y[c].w;
        }
        #pragma unroll
        for (int a = 0; a < 4; a++) {
            int f1 = 4 * I + a;
            #pragma unroll
            for (int c = 0; c < 4; c++) {
                int f2 = 4 * J + c;
                if (f1 <= f2 && f2 < FF) {
                    int p = f1 * FF - (f1 * (f1 - 1)) / 2 + (f2 - f1);
                    dst[p] = __float2half(acc[a][c]);
                }
            }
        }
    } else if (t == 91) {
        #pragma unroll
        for (int q = 0; q < 5; q++) dst[NPAIR + q] = __float2half(0.f);
    }
}

// ---------------- K3: R[d,p] ------------------------------------------------
__global__ void rk_kernel(const float* __restrict__ q) {
    int d = blockIdx.x;
    const float* qd = q + d * FF;
    __half* dst = g_R + (size_t)d * KPAD;
    for (int p = threadIdx.x; p < KPAD; p += 256) {
        float v = 0.f;
        if (p < NPAIR) {
            int f1, f2; pair_of(p, f1, f2);
            v = qd[f1] * qd[f2] * ((f1 == f2) ? 1.f : 2.f);
        }
        dst[p] = __float2half(v);
    }
}

// ---------------- K4: half copy of product_linear ---------------------------
__global__ void plcopy_kernel(const float* __restrict__ pl) {
    size_t i = (size_t)blockIdx.x * 1024 + threadIdx.x;
    if (i < (size_t)DD * FE) g_PL[i] = __float2half(pl[i]);
}

// ---------------- K5: weight transpose to K-major half ----------------------
__global__ void transpose_kernel(const float* __restrict__ W, __half* __restrict__ Wt,
                                 int R, int Cc) {
    __shared__ float tile[32][33];
    int c0 = blockIdx.x * 32, r0 = blockIdx.y * 32;
    int x = threadIdx.x, y = threadIdx.y;      // 32 x 8
    #pragma unroll
    for (int i = 0; i < 32; i += 8)
        tile[y + i][x] = W[(size_t)(r0 + y + i) * Cc + c0 + x];
    __syncthreads();
    #pragma unroll
    for (int i = 0; i < 32; i += 8)
        Wt[(size_t)(c0 + y + i) * R + r0 + x] = __float2half(tile[x][y + i]);
}

// ---------------- fp16 tensor-core GEMM -------------------------------------
// C(16384 x Ntot) = A(16384 x K) @ B(Ntot x K)^T, A/B half K-major.
// CTA 128x128, BK=32, 8 warps (2x4) of 64x32, double-buffered SW128 SMEM,
// ldmatrix fragment loads, m16n8k16 HMMA.
// EPI 0: fp32 store (lz). EPI 1: half store relu(lz+sqrt(max(acc,0))+pbias).
// EPI 2: half store acc+bias, emit per-Mtile column partial sum/sumsq (fp32).
// ABN  : on A staging, a = half(relu(float(a)*aA[k]+aB[k])).
template<int EPI, bool ABN>
__global__ __launch_bounds__(256)
void hgemm(const __half* __restrict__ A, const __half* __restrict__ B,
           void* __restrict__ Cv, int Ntot, int K,
           const float* __restrict__ aA, const float* __restrict__ aB,
           const float* __restrict__ bias,
           const float* __restrict__ lzp, const float* __restrict__ pbias,
           float* __restrict__ statS, float* __restrict__ statQ) {
    extern __shared__ char smem[];   // [A0 8K][B0 8K][A1 8K][B1 8K]
    const uint32_t sb = smem_u32(smem);
    const int tid = threadIdx.x;
    const int l = tid & 31, w = tid >> 5;
    const int wm = w >> 2, wn = w & 3;
    const int m0 = blockIdx.y * 128, n0 = blockIdx.x * 128;
    const int NC = K >> 5;

    // staging coords: thread -> row (0..127), kc2 in {0,2} (16B units)
    const int srow = tid & 127;
    const int kc2  = (tid >> 7) * 2;
    const int sr   = srow & 63;
    const int sh   = srow >> 6;
    const int sOff0 = swz_off(sr, sh * 4 + kc2);
    const int sOff1 = swz_off(sr, sh * 4 + kc2 + 1);

    // ldmatrix per-lane offsets
    uint32_t aoff[4][2], boff[4];
    {
        int mat = l >> 3, rowin = l & 7;
        #pragma unroll
        for (int mi = 0; mi < 4; mi++) {
            int m = wm * 64 + mi * 16 + (mat & 1) * 8 + rowin;
            #pragma unroll
            for (int ks = 0; ks < 2; ks++) {
                int kc = ks * 2 + (mat >> 1);
                aoff[mi][ks] = swz_off(m & 63, (m >> 6) * 4 + kc);
            }
        }
        #pragma unroll
        for (int nj = 0; nj < 4; nj++) {
            int n = wn * 32 + nj * 8 + rowin;
            boff[nj] = swz_off(n & 63, (n >> 6) * 4 + mat);
        }
    }

    const __half* Ap = A + (size_t)(m0 + srow) * K + kc2 * 8;
    const __half* Bp = B + (size_t)(n0 + srow) * K + kc2 * 8;

    float acc[4][4][4];
    #pragma unroll
    for (int i = 0; i < 4; i++)
        #pragma unroll
        for (int j = 0; j < 4; j++)
            #pragma unroll
            for (int r = 0; r < 4; r++) acc[i][j][r] = 0.f;

    // prologue: stage chunk 0
    {
        uint4 a0 = *(const uint4*)(Ap);
        uint4 a1 = *(const uint4*)(Ap + 8);
        if (ABN) {
            int kg = kc2 * 8;
            uint32_t* pw = (uint32_t*)&a0;
            #pragma unroll
            for (int j = 0; j < 4; j++) pw[j] = bnpair(pw[j], aA, aB, kg + 2 * j);
            pw = (uint32_t*)&a1;
            #pragma unroll
            for (int j = 0; j < 4; j++) pw[j] = bnpair(pw[j], aA, aB, kg + 8 + 2 * j);
        }
        uint4 b0 = *(const uint4*)(Bp);
        uint4 b1 = *(const uint4*)(Bp + 8);
        *(uint4*)(smem + sOff0) = a0;
        *(uint4*)(smem + sOff1) = a1;
        *(uint4*)(smem + 8192 + sOff0) = b0;
        *(uint4*)(smem + 8192 + sOff1) = b1;
    }
    __syncthreads();

    for (int c = 0; c < NC; c++) {
        const bool more = (c + 1 < NC);
        uint4 pa0, pa1, pb0, pb1;
        if (more) {
            int kb = (c + 1) * 32;
            pa0 = *(const uint4*)(Ap + kb);
            pa1 = *(const uint4*)(Ap + kb + 8);
            if (ABN) {
                int kg = kb + kc2 * 8;
                uint32_t* pw = (uint32_t*)&pa0;
                #pragma unroll
                for (int j = 0; j < 4; j++) pw[j] = bnpair(pw[j], aA, aB, kg + 2 * j);
                pw = (uint32_t*)&pa1;
                #pragma unroll
                for (int j = 0; j < 4; j++) pw[j] = bnpair(pw[j], aA, aB, kg + 8 + 2 * j);
            }
            pb0 = *(const uint4*)(Bp + kb);
            pb1 = *(const uint4*)(Bp + kb + 8);
        }

        // MMA on current buffer
        const uint32_t SA = sb + (c & 1) * 16384;
        const uint32_t SB = SA + 8192;
        uint32_t bf[4][4];
        #pragma unroll
        for (int nj = 0; nj < 4; nj++) ldsm_x4(bf[nj], SB + boff[nj]);
        #pragma unroll
        for (int ks = 0; ks < 2; ks++) {
            uint32_t af[4][4];
            #pragma unroll
            for (int mi = 0; mi < 4; mi++) ldsm_x4(af[mi], SA + aoff[mi][ks]);
            #pragma unroll
            for (int mi = 0; mi < 4; mi++)
                #pragma unroll
                for (int nj = 0; nj < 4; nj++)
                    mma16(acc[mi][nj], af[mi], &bf[nj][ks * 2]);
        }

        if (more) {
            char* dst = smem + ((c + 1) & 1) * 16384;
            *(uint4*)(dst + sOff0) = pa0;
            *(uint4*)(dst + sOff1) = pa1;
            *(uint4*)(dst + 8192 + sOff0) = pb0;
            *(uint4*)(dst + 8192 + sOff1) = pb1;
            __syncthreads();
        }
    }

    // ---- epilogue ----
    float* Cf = (float*)Cv;
    __half* Ch = (__half*)Cv;
    const int r0 = m0 + wm * 64 + (l >> 2);
    const int c0b = n0 + wn * 32 + (l & 3) * 2;
    float sS[4][2] = {}, sQ[4][2] = {};
    #pragma unroll
    for (int mi = 0; mi < 4; mi++) {
        int r = r0 + mi * 16;
        #pragma unroll
        for (int nj = 0; nj < 4; nj++) {
            int cc = c0b + nj * 8;
            float d0 = acc[mi][nj][0], d1 = acc[mi][nj][1];
            float d2 = acc[mi][nj][2], d3 = acc[mi][nj][3];
            if (EPI == 0) {
                *(float2*)(Cf + (size_t)r * Ntot + cc)       = make_float2(d0, d1);
                *(float2*)(Cf + (size_t)(r + 8) * Ntot + cc) = make_float2(d2, d3);
            } else if (EPI == 1) {
                d0 = fmaxf(0.f, lzp[(size_t)r * Ntot + cc]           + sqrtf(fmaxf(d0, 0.f)) + pbias[cc]);
                d1 = fmaxf(0.f, lzp[(size_t)r * Ntot + cc + 1]       + sqrtf(fmaxf(d1, 0.f)) + pbias[cc + 1]);
                d2 = fmaxf(0.f, lzp[(size_t)(r + 8) * Ntot + cc]     + sqrtf(fmaxf(d2, 0.f)) + pbias[cc]);
                d3 = fmaxf(0.f, lzp[(size_t)(r + 8) * Ntot + cc + 1] + sqrtf(fmaxf(d3, 0.f)) + pbias[cc + 1]);
                *(__half2*)(Ch + (size_t)r * Ntot + cc)       = __floats2half2_rn(d0, d1);
                *(__half2*)(Ch + (size_t)(r + 8) * Ntot + cc) = __floats2half2_rn(d2, d3);
            } else {
                float b0v = bias[cc], b1v = bias[cc + 1];
                d0 += b0v; d1 += b1v; d2 += b0v; d3 += b1v;
                sS[nj][0] += d0 + d2;           sS[nj][1] += d1 + d3;
                sQ[nj][0] += d0 * d0 + d2 * d2; sQ[nj][1] += d1 * d1 + d3 * d3;
                *(__half2*)(Ch + (size_t)r * Ntot + cc)       = __floats2half2_rn(d0, d1);
                *(__half2*)(Ch + (size_t)(r + 8) * Ntot + cc) = __floats2half2_rn(d2, d3);
            }
        }
    }
    if (EPI == 2) {
        #pragma unroll
        for (int nj = 0; nj < 4; nj++)
            #pragma unroll
            for (int e = 0; e < 2; e++) {
                #pragma unroll
                for (int off = 4; off < 32; off <<= 1) {
                    sS[nj][e] += __shfl_xor_sync(0xffffffffu, sS[nj][e], off);
                    sQ[nj][e] += __shfl_xor_sync(0xffffffffu, sQ[nj][e], off);
                }
            }
        float* sf = (float*)smem;
        __syncthreads();
        if ((l >> 2) == 0) {
            #pragma unroll
            for (int nj = 0; nj < 4; nj++)
                #pragma unroll
                for (int e = 0; e < 2; e++) {
                    int cl = wn * 32 + nj * 8 + (l & 3) * 2 + e;
                    sf[wm * 128 + cl]       = sS[nj][e];
                    sf[256 + wm * 128 + cl] = sQ[nj][e];
                }
        }
        __syncthreads();
        if (tid < 128) {
            statS[(size_t)blockIdx.y * Ntot + n0 + tid] = sf[tid] + sf[128 + tid];
            statQ[(size_t)blockIdx.y * Ntot + n0 + tid] = sf[256 + tid] + sf[384 + tid];
        }
    }
}

// ---------------- BN finalize ----------------------------------------------
__global__ void bnfin_kernel(const float* __restrict__ pS,
                             const float* __restrict__ pQ, int H,
                             const float* __restrict__ scale,
                             const float* __restrict__ offset,
                             float* __restrict__ oA, float* __restrict__ oB) {
    int c = blockIdx.x * blockDim.x + threadIdx.x;
    if (c >= H) return;
    float s = 0.f, q = 0.f;
    for (int t = 0; t < 128; t++) { s += pS[t * H + c]; q += pQ[t * H + c]; }
    float m = s * (1.f / (float)BATCH);
    float v = q * (1.f / (float)BATCH) - m * m;
    float a = scale[0] * rsqrtf(fmaxf(v, 0.f) + 1e-10f);
    oA[c] = a;
    oB[c] = offset[0] - m * a;
}

// ---------------- output head ----------------------------------------------
__global__ void out_kernel(const float* __restrict__ w,
                           const float* __restrict__ ob,
                           float* __restrict__ out) {
    int b = blockIdx.x;
    int tid = threadIdx.x;   // 128 threads
    const __half* row = g_y2h + (size_t)b * HH2;
    float s = 0.f;
    #pragma unroll
    for (int n = tid; n < HH2; n += 128) {
        float v = fmaxf(0.f, fmaf(__half2float(row[n]), g_bnA2[n], g_bnB2[n]));
        s += v * w[n];
    }
    __shared__ float red[128];
    red[tid] = s;
    __syncthreads();
    for (int off = 64; off > 0; off >>= 1) {
        if (tid < off) red[tid] += red[tid + off];
        __syncthreads();
    }
    if (tid == 0) {
        float x = red[0] + ob[0];
        out[b] = 1.f / (1.f + expf(-x));
    }
}

// ---------------- launch ----------------------------------------------------
extern "C" void kernel_launch(void* const* d_in, const int* in_sizes, int n_in,
                              void* d_out, int out_size) {
    const int*   fidx  = (const int*)  d_in[0];
    const float* fval  = (const float*)d_in[1];
    const float* femb  = (const float*)d_in[2];
    const float* pl    = (const float*)d_in[3];
    const float* pbias = (const float*)d_in[4];
    const float* pq    = (const float*)d_in[5];
    const float* W0    = (const float*)d_in[6];
    const float* b0    = (const float*)d_in[7];
    const float* W1    = (const float*)d_in[8];
    const float* b1    = (const float*)d_in[9];
    const float* bnS   = (const float*)d_in[10];
    const float* bnO   = (const float*)d_in[11];
    const float* ow    = (const float*)d_in[12];
    const float* ob    = (const float*)d_in[13];
    float* out = (float*)d_out;

    void *emb, *gram, *PL, *R, *W0t, *W1t, *y0h, *y1h, *y2h, *lz, *pS, *pQ;
    void *A1, *B1, *A2, *B2;
    cudaGetSymbolAddress(&emb,  g_emb);
    cudaGetSymbolAddress(&gram, g_gram);
    cudaGetSymbolAddress(&PL,   g_PL);
    cudaGetSymbolAddress(&R,    g_R);
    cudaGetSymbolAddress(&W0t,  g_W0t);
    cudaGetSymbolAddress(&W1t,  g_W1t);
    cudaGetSymbolAddress(&y0h,  g_y0h);
    cudaGetSymbolAddress(&y1h,  g_y1h);
    cudaGetSymbolAddress(&y2h,  g_y2h);
    cudaGetSymbolAddress(&lz,   g_lz);
    cudaGetSymbolAddress(&pS,   g_pS);
    cudaGetSymbolAddress(&pQ,   g_pQ);
    cudaGetSymbolAddress(&A1,   g_bnA1);
    cudaGetSymbolAddress(&B1,   g_bnB1);
    cudaGetSymbolAddress(&A2,   g_bnA2);
    cudaGetSymbolAddress(&B2,   g_bnB2);

    const int SMEM = 32768;

    // order chosen so launch index 3 (the ncu-captured one) is the big LZ GEMM
    embed_kernel<<<(BATCH * FF) / 4, 256>>>(fidx, fval, femb);                  // 0
    plcopy_kernel<<<(DD * FE + 1023) / 1024, 1024>>>(pl);                       // 1
    gram_kernel<<<BATCH / 2, 256>>>();                                          // 2
    // 3: LZ = emb @ PL^T  (N=512, K=3200)  <-- profiled launch
    hgemm<0, false><<<dim3(4, 128), 256, SMEM>>>(
        (const __half*)emb, (const __half*)PL, lz, DD, FE,
        nullptr, nullptr, nullptr, nullptr, nullptr, nullptr, nullptr);
    rk_kernel<<<DD, 256>>>(pq);                                                 // 4
    // y0 = relu(lz + sqrt(G @ R^T) + pbias)  (N=512, K=1280)
    hgemm<1, false><<<dim3(4, 128), 256, SMEM>>>(
        (const __half*)gram, (const __half*)R, y0h, DD, KPAD,
        nullptr, nullptr, nullptr, (const float*)lz, pbias, nullptr, nullptr);
    transpose_kernel<<<dim3(HH1 / 32, DD / 32), dim3(32, 8)>>>(W0, (__half*)W0t, DD, HH1);
    // y1 = y0 @ W0 + b0  (N=1024, K=512) + BN partials
    hgemm<2, false><<<dim3(8, 128), 256, SMEM>>>(
        (const __half*)y0h, (const __half*)W0t, y1h, HH1, DD,
        nullptr, nullptr, b0, nullptr, nullptr, (float*)pS, (float*)pQ);
    bnfin_kernel<<<HH1 / 256, 256>>>((const float*)pS, (const float*)pQ, HH1,
                                     bnS, bnO, (float*)A1, (float*)B1);
    transpose_kernel<<<dim3(HH2 / 32, HH1 / 32), dim3(32, 8)>>>(W1, (__half*)W1t, HH1, HH2);
    // y2 = bnrelu(y1) @ W1 + b1  (N=512, K=1024) + BN partials
    hgemm<2, true><<<dim3(4, 128), 256, SMEM>>>(
        (const __half*)y1h, (const __half*)W1t, y2h, HH2, HH1,
        (const float*)A1, (const float*)B1, b1, nullptr, nullptr,
        (float*)pS, (float*)pQ);
    bnfin_kernel<<<HH2 / 256, 256>>>((const float*)pS, (const float*)pQ, HH2,
                                     bnS, bnO, (float*)A2, (float*)B2);
    // head
    out_kernel<<<BATCH, 128>>>(ow, ob, out);
}

// round 5
// speedup vs baseline: 3.6385x; 1.4223x over previous
#include <cuda_runtime.h>
#include <cuda_fp16.h>
#include <math.h>
#include <cstdint>

// Problem dims
#define BATCH 16384
#define FF    50
#define EE    64
#define FE    3200      // F*E
#define DD    512
#define NPAIR 1275      // F*(F+1)/2
#define KPAD  1280      // NPAIR padded to mult of 32
#define HH1   1024
#define HH2   512

// ---------------- scratch ----------------------------------------------------
__device__ __half g_emb [(size_t)BATCH * FE];
__device__ __half g_gram[(size_t)BATCH * KPAD];
__device__ __half g_PL  [(size_t)DD * FE];
__device__ __half g_R   [(size_t)DD * KPAD];
__device__ __half g_W0t [(size_t)HH1 * DD];
__device__ __half g_W1t [(size_t)HH2 * HH1];
__device__ __half g_y0h [(size_t)BATCH * DD];
__device__ __half g_y1h [(size_t)BATCH * HH1];
__device__ __half g_y2h [(size_t)BATCH * HH2];
__device__ float  g_lz  [(size_t)BATCH * DD];
__device__ float  g_pS  [64 * HH1];
__device__ float  g_pQ  [64 * HH1];
__device__ float  g_bnA1[HH1], g_bnB1[HH1];
__device__ float  g_bnA2[HH2], g_bnB2[HH2];

// ---------------- helpers -----------------------------------------------------
__device__ __forceinline__ uint32_t smem_u32(const void* p) {
    uint32_t a;
    asm("{ .reg .u64 t; cvta.to.shared.u64 t, %1; cvt.u32.u64 %0, t; }"
        : "=r"(a) : "l"(p));
    return a;
}

__device__ __forceinline__ void ldsm_x4(uint32_t r[4], uint32_t addr) {
    asm volatile("ldmatrix.sync.aligned.m8n8.x4.shared.b16 {%0,%1,%2,%3}, [%4];"
        : "=r"(r[0]), "=r"(r[1]), "=r"(r[2]), "=r"(r[3]) : "r"(addr));
}

__device__ __forceinline__ void mma16(float d[4], const uint32_t a[4], const uint32_t b[2]) {
    asm volatile(
        "mma.sync.aligned.m16n8k16.row.col.f32.f16.f16.f32 "
        "{%0,%1,%2,%3}, {%4,%5,%6,%7}, {%8,%9}, {%0,%1,%2,%3};"
        : "+f"(d[0]), "+f"(d[1]), "+f"(d[2]), "+f"(d[3])
        : "r"(a[0]), "r"(a[1]), "r"(a[2]), "r"(a[3]), "r"(b[0]), "r"(b[1]));
}

__device__ __forceinline__ uint32_t bnpair(uint32_t w, const float* __restrict__ aA,
                                           const float* __restrict__ aB, int kg) {
    __half2 h = *reinterpret_cast<__half2*>(&w);
    float x = __low2float(h), y = __high2float(h);
    x = fmaxf(0.f, fmaf(x, aA[kg], aB[kg]));
    y = fmaxf(0.f, fmaf(y, aA[kg + 1], aB[kg + 1]));
    __half2 r = __floats2half2_rn(x, y);
    return *reinterpret_cast<uint32_t*>(&r);
}

__device__ __forceinline__ void pair_of(int p, int& f1, int& f2) {
    int a = 0, rem = p;
    while (rem >= FF - a) { rem -= FF - a; a++; }
    f1 = a; f2 = a + rem;
}

// SW128 tile offset: 64 rows x 128B; (row 0..63, 16B-col 0..7)
__device__ __forceinline__ int swz_off(int r, int cc) {
    return r * 128 + 16 * (cc ^ (r & 7));
}

// ---------------- K1: embedding gather ----------------------------------------
__global__ void embed_kernel(const int* __restrict__ fidx,
                             const float* __restrict__ fval,
                             const float* __restrict__ femb) {
    int t = threadIdx.x;
    int e = t & 63;
    int row = blockIdx.x * 4 + (t >> 6);
    int i = fidx[row];
    float v = fval[row];
    g_emb[(size_t)row * EE + e] = __float2half(femb[(size_t)i * EE + e] * v);
}

// ---------------- K2: Gram via tensor cores -----------------------------------
// Per batch b: C = E(64x64) @ E^T, E = emb rows (50 real, 64 padded).
// 2 batches/CTA; 4 warps/batch, each computing a 16x64 strip.
__global__ __launch_bounds__(256)
void gram_mma_kernel() {
    __shared__ __align__(16) char sm[2 * 8192 + 2 * 64 * 72 * 2];
    const int tid = threadIdx.x;
    const int hb_id = tid >> 7;          // batch within CTA
    const int t = tid & 127;
    const int w4 = (tid >> 5) & 3;       // warp within batch
    const int l = tid & 31;
    const size_t b = (size_t)blockIdx.x * 2 + hb_id;

    char* E = sm + hb_id * 8192;
    __half* Cb = (__half*)(sm + 16384) + hb_id * 64 * 72;

    // stage E: 64 rows x 128B (rows >= 50 zero), swizzled
    {
        int row = t >> 1, hb = t & 1;
        const __half* src = g_emb + b * FE + (size_t)row * EE + hb * 32;
        #pragma unroll
        for (int j = 0; j < 4; j++) {
            uint4 v = make_uint4(0, 0, 0, 0);
            if (row < FF) v = *(const uint4*)(src + j * 8);
            *(uint4*)(E + swz_off(row, hb * 4 + j)) = v;
        }
    }
    __syncthreads();

    const uint32_t Eb = smem_u32(E);
    const int mat = l >> 3, rowin = l & 7;

    // A fragment offsets: strip rows w4*16..+16, ks 0..3
    uint32_t aoff[4];
    {
        int m = w4 * 16 + (mat & 1) * 8 + rowin;
        #pragma unroll
        for (int ks = 0; ks < 4; ks++)
            aoff[ks] = Eb + swz_off(m, ks * 2 + (mat >> 1));
    }
    // B fragment offsets (same tile): nj 0..7, kk 0..1
    uint32_t bf[8][8];
    #pragma unroll
    for (int nj = 0; nj < 8; nj++) {
        int n = nj * 8 + rowin;
        #pragma unroll
        for (int kk = 0; kk < 2; kk++)
            ldsm_x4(&bf[nj][kk * 4], Eb + swz_off(n, kk * 4 + mat));
    }

    float acc[8][4];
    #pragma unroll
    for (int nj = 0; nj < 8; nj++)
        #pragma unroll
        for (int q = 0; q < 4; q++) acc[nj][q] = 0.f;

    #pragma unroll
    for (int ks = 0; ks < 4; ks++) {
        uint32_t af[4];
        ldsm_x4(af, aoff[ks]);
        #pragma unroll
        for (int nj = 0; nj < 8; nj++)
            mma16(acc[nj], af, &bf[nj][ks * 2]);
    }

    // write strip to staging
    {
        int r = w4 * 16 + (l >> 2);
        int c = (l & 3) * 2;
        #pragma unroll
        for (int nj = 0; nj < 8; nj++) {
            int cc = c + nj * 8;
            Cb[r * 72 + cc]           = __float2half(acc[nj][0]);
            Cb[r * 72 + cc + 1]       = __float2half(acc[nj][1]);
            Cb[(r + 8) * 72 + cc]     = __float2half(acc[nj][2]);
            Cb[(r + 8) * 72 + cc + 1] = __float2half(acc[nj][3]);
        }
    }
    __syncthreads();

    // packed upper-triangle copy: gram[b, p(f1,f2)] = C[f1][f2], f1<=f2
    __half* dst = g_gram + b * KPAD;
    int base = 0;
    for (int f1 = 0; f1 < FF; f1++) {
        int cnt = FF - f1;
        if (t < cnt) dst[base + t] = Cb[f1 * 72 + f1 + t];
        base += cnt;
    }
    if (t < KPAD - NPAIR) dst[NPAIR + t] = __float2half(0.f);
}

// ---------------- K3: R[d,p] ---------------------------------------------------
__global__ void rk_kernel(const float* __restrict__ q) {
    int d = blockIdx.x;
    const float* qd = q + d * FF;
    __half* dst = g_R + (size_t)d * KPAD;
    for (int p = threadIdx.x; p < KPAD; p += 256) {
        float v = 0.f;
        if (p < NPAIR) {
            int f1, f2; pair_of(p, f1, f2);
            v = qd[f1] * qd[f2] * ((f1 == f2) ? 1.f : 2.f);
        }
        dst[p] = __float2half(v);
    }
}

// ---------------- K4: half copy of product_linear -------------------------------
__global__ void plcopy_kernel(const float* __restrict__ pl) {
    size_t i = (size_t)blockIdx.x * 1024 + threadIdx.x;
    if (i < (size_t)DD * FE) g_PL[i] = __float2half(pl[i]);
}

// ---------------- K5: weight transpose to K-major half --------------------------
__global__ void transpose_kernel(const float* __restrict__ W, __half* __restrict__ Wt,
                                 int R, int Cc) {
    __shared__ float tile[32][33];
    int c0 = blockIdx.x * 32, r0 = blockIdx.y * 32;
    int x = threadIdx.x, y = threadIdx.y;      // 32 x 8
    #pragma unroll
    for (int i = 0; i < 32; i += 8)
        tile[y + i][x] = W[(size_t)(r0 + y + i) * Cc + c0 + x];
    __syncthreads();
    #pragma unroll
    for (int i = 0; i < 32; i += 8)
        Wt[(size_t)(c0 + y + i) * R + r0 + x] = __float2half(tile[x][y + i]);
}

// ---------------- fp16 tensor-core GEMM, CTA 256x128, warp 64x64 ---------------
// C(16384 x Ntot) = A(16384 x K) @ B(Ntot x K)^T, half K-major operands.
// BK=32, 8 warps (4m x 2n), double-buffered swizzled SMEM, ldmatrix + m16n8k16.
// EPI 0: fp32 store. EPI 1: half relu(lz+sqrt(max(acc,0))+pbias).
// EPI 2: half acc+bias + per-Mtile column partial sum/sumsq.
// ABN  : BN+relu applied to A on staging (along K).
template<int EPI, bool ABN>
__global__ __launch_bounds__(256)
void hgemm(const __half* __restrict__ A, const __half* __restrict__ B,
           void* __restrict__ Cv, int Ntot, int K,
           const float* __restrict__ aA, const float* __restrict__ aB,
           const float* __restrict__ bias,
           const float* __restrict__ lzp, const float* __restrict__ pbias,
           float* __restrict__ statS, float* __restrict__ statQ) {
    extern __shared__ char smem[];   // per buf: [A 16K][B 8K], x2
    const uint32_t sb = smem_u32(smem);
    const int tid = threadIdx.x;
    const int l = tid & 31, w = tid >> 5;
    const int wm = w >> 1, wn = w & 1;
    const int m0 = blockIdx.y * 256, n0 = blockIdx.x * 128;
    const int NC = K >> 5;

    // staging maps
    const int arow = tid;                          // A row 0..255
    int aoffS[4];
    {
        int tile = (arow >> 7) * 8192;
        int sr = arow & 63, sh = (arow >> 6) & 1;
        #pragma unroll
        for (int j = 0; j < 4; j++) aoffS[j] = tile + swz_off(sr, sh * 4 + j);
    }
    const int brow = tid >> 1, bhb = tid & 1;      // B row 0..127
    int boffS[2];
    {
        int sr = brow & 63, sh = brow >> 6;
        #pragma unroll
        for (int j = 0; j < 2; j++) boffS[j] = 16384 + swz_off(sr, sh * 4 + bhb * 2 + j);
    }
    const __half* Ap = A + (size_t)(m0 + arow) * K;
    const __half* Bp = B + (size_t)(n0 + brow) * K + bhb * 16;

    // ldmatrix maps
    const int mat = l >> 3, rowin = l & 7;
    uint32_t aoff[4][2], boff[8];
    #pragma unroll
    for (int mi = 0; mi < 4; mi++) {
        int m = wm * 64 + mi * 16 + (mat & 1) * 8 + rowin;
        int tile = (m >> 7) * 8192;
        int lr = m & 127, sr = lr & 63, sh = lr >> 6;
        #pragma unroll
        for (int ks = 0; ks < 2; ks++)
            aoff[mi][ks] = tile + swz_off(sr, sh * 4 + ks * 2 + (mat >> 1));
    }
    #pragma unroll
    for (int nj = 0; nj < 8; nj++) {
        int n = wn * 64 + nj * 8 + rowin;
        boff[nj] = 16384 + swz_off(n & 63, (n >> 6) * 4 + mat);
    }

    float acc[4][8][4];
    #pragma unroll
    for (int mi = 0; mi < 4; mi++)
        #pragma unroll
        for (int nj = 0; nj < 8; nj++)
            #pragma unroll
            for (int q = 0; q < 4; q++) acc[mi][nj][q] = 0.f;

    // prologue: stage chunk 0 into buf 0
    {
        #pragma unroll
        for (int j = 0; j < 4; j++) {
            uint4 v = *(const uint4*)(Ap + j * 8);
            if (ABN) {
                uint32_t* pw = (uint32_t*)&v;
                #pragma unroll
                for (int jj = 0; jj < 4; jj++) pw[jj] = bnpair(pw[jj], aA, aB, j * 8 + 2 * jj);
            }
            *(uint4*)(smem + aoffS[j]) = v;
        }
        #pragma unroll
        for (int j = 0; j < 2; j++)
            *(uint4*)(smem + boffS[j]) = *(const uint4*)(Bp + j * 8);
    }
    __syncthreads();

    for (int c = 0; c < NC; c++) {
        const bool more = (c + 1 < NC);
        uint4 pa[4], pb[2];
        if (more) {
            int kb = (c + 1) * 32;
            #pragma unroll
            for (int j = 0; j < 4; j++) {
                uint4 v = *(const uint4*)(Ap + kb + j * 8);
                if (ABN) {
                    uint32_t* pw = (uint32_t*)&v;
                    #pragma unroll
                    for (int jj = 0; jj < 4; jj++)
                        pw[jj] = bnpair(pw[jj], aA, aB, kb + j * 8 + 2 * jj);
                }
                pa[j] = v;
            }
            #pragma unroll
            for (int j = 0; j < 2; j++) pb[j] = *(const uint4*)(Bp + kb + j * 8);
        }

        const uint32_t SA = sb + (c & 1) * 24576;
        uint32_t bf[8][4];
        #pragma unroll
        for (int nj = 0; nj < 8; nj++) ldsm_x4(bf[nj], SA + boff[nj]);
        #pragma unroll
        for (int ks = 0; ks < 2; ks++) {
            uint32_t af[4][4];
            #pragma unroll
            for (int mi = 0; mi < 4; mi++) ldsm_x4(af[mi], SA + aoff[mi][ks]);
            #pragma unroll
            for (int mi = 0; mi < 4; mi++)
                #pragma unroll
                for (int nj = 0; nj < 8; nj++)
                    mma16(acc[mi][nj], af[mi], &bf[nj][ks * 2]);
        }

        if (more) {
            char* dstb = smem + ((c + 1) & 1) * 24576;
            #pragma unroll
            for (int j = 0; j < 4; j++) *(uint4*)(dstb + aoffS[j]) = pa[j];
            #pragma unroll
            for (int j = 0; j < 2; j++) *(uint4*)(dstb + boffS[j]) = pb[j];
            __syncthreads();
        }
    }

    // ---- epilogue ----
    float* Cf = (float*)Cv;
    __half* Ch = (__half*)Cv;
    const int r0 = m0 + wm * 64 + (l >> 2);
    const int c0b = n0 + wn * 64 + (l & 3) * 2;
    float sS[8][2] = {}, sQ[8][2] = {};
    #pragma unroll
    for (int mi = 0; mi < 4; mi++) {
        int r = r0 + mi * 16;
        #pragma unroll
        for (int nj = 0; nj < 8; nj++) {
            int cc = c0b + nj * 8;
            float d0 = acc[mi][nj][0], d1 = acc[mi][nj][1];
            float d2 = acc[mi][nj][2], d3 = acc[mi][nj][3];
            if (EPI == 0) {
                *(float2*)(Cf + (size_t)r * Ntot + cc)       = make_float2(d0, d1);
                *(float2*)(Cf + (size_t)(r + 8) * Ntot + cc) = make_float2(d2, d3);
            } else if (EPI == 1) {
                d0 = fmaxf(0.f, lzp[(size_t)r * Ntot + cc]           + sqrtf(fmaxf(d0, 0.f)) + pbias[cc]);
                d1 = fmaxf(0.f, lzp[(size_t)r * Ntot + cc + 1]       + sqrtf(fmaxf(d1, 0.f)) + pbias[cc + 1]);
                d2 = fmaxf(0.f, lzp[(size_t)(r + 8) * Ntot + cc]     + sqrtf(fmaxf(d2, 0.f)) + pbias[cc]);
                d3 = fmaxf(0.f, lzp[(size_t)(r + 8) * Ntot + cc + 1] + sqrtf(fmaxf(d3, 0.f)) + pbias[cc + 1]);
                *(__half2*)(Ch + (size_t)r * Ntot + cc)       = __floats2half2_rn(d0, d1);
                *(__half2*)(Ch + (size_t)(r + 8) * Ntot + cc) = __floats2half2_rn(d2, d3);
            } else {
                float b0v = bias[cc], b1v = bias[cc + 1];
                d0 += b0v; d1 += b1v; d2 += b0v; d3 += b1v;
                sS[nj][0] += d0 + d2;           sS[nj][1] += d1 + d3;
                sQ[nj][0] += d0 * d0 + d2 * d2; sQ[nj][1] += d1 * d1 + d3 * d3;
                *(__half2*)(Ch + (size_t)r * Ntot + cc)       = __floats2half2_rn(d0, d1);
                *(__half2*)(Ch + (size_t)(r + 8) * Ntot + cc) = __floats2half2_rn(d2, d3);
            }
        }
    }
    if (EPI == 2) {
        #pragma unroll
        for (int nj = 0; nj < 8; nj++)
            #pragma unroll
            for (int e = 0; e < 2; e++) {
                #pragma unroll
                for (int off = 4; off < 32; off <<= 1) {
                    sS[nj][e] += __shfl_xor_sync(0xffffffffu, sS[nj][e], off);
                    sQ[nj][e] += __shfl_xor_sync(0xffffffffu, sQ[nj][e], off);
                }
            }
        float* sf = (float*)smem;
        __syncthreads();
        if (l < 4) {
            #pragma unroll
            for (int nj = 0; nj < 8; nj++)
                #pragma unroll
                for (int e = 0; e < 2; e++) {
                    int cl = wn * 64 + nj * 8 + (l & 3) * 2 + e;
                    sf[wm * 128 + cl]       = sS[nj][e];
                    sf[512 + wm * 128 + cl] = sQ[nj][e];
                }
        }
        __syncthreads();
        if (tid < 128) {
            float s = sf[tid] + sf[128 + tid] + sf[256 + tid] + sf[384 + tid];
            float q = sf[512 + tid] + sf[640 + tid] + sf[768 + tid] + sf[896 + tid];
            statS[(size_t)blockIdx.y * Ntot + n0 + tid] = s;
            statQ[(size_t)blockIdx.y * Ntot + n0 + tid] = q;
        }
    }
}

// ---------------- BN finalize ----------------------------------------------
__global__ void bnfin_kernel(const float* __restrict__ pS,
                             const float* __restrict__ pQ, int H,
                             const float* __restrict__ scale,
                             const float* __restrict__ offset,
                             float* __restrict__ oA, float* __restrict__ oB) {
    int c = blockIdx.x * blockDim.x + threadIdx.x;
    if (c >= H) return;
    float s = 0.f, q = 0.f;
    for (int t = 0; t < 64; t++) { s += pS[t * H + c]; q += pQ[t * H + c]; }
    float m = s * (1.f / (float)BATCH);
    float v = q * (1.f / (float)BATCH) - m * m;
    float a = scale[0] * rsqrtf(fmaxf(v, 0.f) + 1e-10f);
    oA[c] = a;
    oB[c] = offset[0] - m * a;
}

// ---------------- output head ----------------------------------------------
__global__ void out_kernel(const float* __restrict__ w,
                           const float* __restrict__ ob,
                           float* __restrict__ out) {
    int b = blockIdx.x;
    int tid = threadIdx.x;   // 128 threads
    const __half* row = g_y2h + (size_t)b * HH2;
    float s = 0.f;
    #pragma unroll
    for (int n = tid; n < HH2; n += 128) {
        float v = fmaxf(0.f, fmaf(__half2float(row[n]), g_bnA2[n], g_bnB2[n]));
        s += v * w[n];
    }
    __shared__ float red[128];
    red[tid] = s;
    __syncthreads();
    for (int off = 64; off > 0; off >>= 1) {
        if (tid < off) red[tid] += red[tid + off];
        __syncthreads();
    }
    if (tid == 0) {
        float x = red[0] + ob[0];
        out[b] = 1.f / (1.f + expf(-x));
    }
}

// ---------------- launch ----------------------------------------------------
extern "C" void kernel_launch(void* const* d_in, const int* in_sizes, int n_in,
                              void* d_out, int out_size) {
    const int*   fidx  = (const int*)  d_in[0];
    const float* fval  = (const float*)d_in[1];
    const float* femb  = (const float*)d_in[2];
    const float* pl    = (const float*)d_in[3];
    const float* pbias = (const float*)d_in[4];
    const float* pq    = (const float*)d_in[5];
    const float* W0    = (const float*)d_in[6];
    const float* b0    = (const float*)d_in[7];
    const float* W1    = (const float*)d_in[8];
    const float* b1    = (const float*)d_in[9];
    const float* bnS   = (const float*)d_in[10];
    const float* bnO   = (const float*)d_in[11];
    const float* ow    = (const float*)d_in[12];
    const float* ob    = (const float*)d_in[13];
    float* out = (float*)d_out;

    void *emb, *gram, *PL, *R, *W0t, *W1t, *y0h, *y1h, *y2h, *lz, *pS, *pQ;
    void *A1, *B1, *A2, *B2;
    cudaGetSymbolAddress(&emb,  g_emb);
    cudaGetSymbolAddress(&gram, g_gram);
    cudaGetSymbolAddress(&PL,   g_PL);
    cudaGetSymbolAddress(&R,    g_R);
    cudaGetSymbolAddress(&W0t,  g_W0t);
    cudaGetSymbolAddress(&W1t,  g_W1t);
    cudaGetSymbolAddress(&y0h,  g_y0h);
    cudaGetSymbolAddress(&y1h,  g_y1h);
    cudaGetSymbolAddress(&y2h,  g_y2h);
    cudaGetSymbolAddress(&lz,   g_lz);
    cudaGetSymbolAddress(&pS,   g_pS);
    cudaGetSymbolAddress(&pQ,   g_pQ);
    cudaGetSymbolAddress(&A1,   g_bnA1);
    cudaGetSymbolAddress(&B1,   g_bnB1);
    cudaGetSymbolAddress(&A2,   g_bnA2);
    cudaGetSymbolAddress(&B2,   g_bnB2);

    const int SMEM = 49152;
    cudaFuncSetAttribute(hgemm<0, false>, cudaFuncAttributeMaxDynamicSharedMemorySize, SMEM);
    cudaFuncSetAttribute(hgemm<1, false>, cudaFuncAttributeMaxDynamicSharedMemorySize, SMEM);
    cudaFuncSetAttribute(hgemm<2, false>, cudaFuncAttributeMaxDynamicSharedMemorySize, SMEM);
    cudaFuncSetAttribute(hgemm<2, true >, cudaFuncAttributeMaxDynamicSharedMemorySize, SMEM);

    embed_kernel<<<(BATCH * FF) / 4, 256>>>(fidx, fval, femb);                  // 0
    plcopy_kernel<<<(DD * FE + 1023) / 1024, 1024>>>(pl);                       // 1
    gram_mma_kernel<<<BATCH / 2, 256>>>();                                       // 2
    // 3: LZ = emb @ PL^T  (N=512, K=3200)  <-- profiled launch
    hgemm<0, false><<<dim3(4, 64), 256, SMEM>>>(
        (const __half*)emb, (const __half*)PL, lz, DD, FE,
        nullptr, nullptr, nullptr, nullptr, nullptr, nullptr, nullptr);
    rk_kernel<<<DD, 256>>>(pq);                                                  // 4
    // y0 = relu(lz + sqrt(G @ R^T) + pbias)  (N=512, K=1280)
    hgemm<1, false><<<dim3(4, 64), 256, SMEM>>>(
        (const __half*)gram, (const __half*)R, y0h, DD, KPAD,
        nullptr, nullptr, nullptr, (const float*)lz, pbias, nullptr, nullptr);
    transpose_kernel<<<dim3(HH1 / 32, DD / 32), dim3(32, 8)>>>(W0, (__half*)W0t, DD, HH1);
    // y1 = y0 @ W0 + b0  (N=1024, K=512) + BN partials
    hgemm<2, false><<<dim3(8, 64), 256, SMEM>>>(
        (const __half*)y0h, (const __half*)W0t, y1h, HH1, DD,
        nullptr, nullptr, b0, nullptr, nullptr, (float*)pS, (float*)pQ);
    bnfin_kernel<<<HH1 / 256, 256>>>((const float*)pS, (const float*)pQ, HH1,
                                     bnS, bnO, (float*)A1, (float*)B1);
    transpose_kernel<<<dim3(HH2 / 32, HH1 / 32), dim3(32, 8)>>>(W1, (__half*)W1t, HH1, HH2);
    // y2 = bnrelu(y1) @ W1 + b1  (N=512, K=1024) + BN partials
    hgemm<2, true><<<dim3(4, 64), 256, SMEM>>>(
        (const __half*)y1h, (const __half*)W1t, y2h, HH2, HH1,
        (const float*)A1, (const float*)B1, b1, nullptr, nullptr,
        (float*)pS, (float*)pQ);
    bnfin_kernel<<<HH2 / 256, 256>>>((const float*)pS, (const float*)pQ, HH2,
                                     bnS, bnO, (float*)A2, (float*)B2);
    out_kernel<<<BATCH, 128>>>(ow, ob, out);
}

// round 6
// speedup vs baseline: 4.3302x; 1.1901x over previous
#include <cuda_runtime.h>
#include <cuda_fp16.h>
#include <math.h>
#include <cstdint>

// Problem dims
#define BATCH 16384
#define FF    50
#define EE    64
#define FE    3200      // F*E
#define DD    512
#define NPAIR 1275      // F*(F+1)/2
#define KPAD  1280
#define HH1   1024
#define HH2   512

// ---------------- scratch ----------------------------------------------------
__device__ __half g_emb [(size_t)BATCH * FE];
__device__ __half g_gram[(size_t)BATCH * KPAD];
__device__ __half g_PL  [(size_t)DD * FE];
__device__ __half g_R   [(size_t)DD * KPAD];
__device__ __half g_W0t [(size_t)HH1 * DD];
__device__ __half g_W1t [(size_t)HH2 * HH1];
__device__ __half g_y0h [(size_t)BATCH * DD];
__device__ __half g_y1h [(size_t)BATCH * HH1];
__device__ __half g_y2h [(size_t)BATCH * HH2];
__device__ float  g_lz  [(size_t)BATCH * DD];
__device__ float  g_pS  [128 * HH1];
__device__ float  g_pQ  [128 * HH1];
__device__ float  g_bnA1[HH1], g_bnB1[HH1];
__device__ float  g_bnA2[HH2], g_bnB2[HH2];

// ---------------- helpers -----------------------------------------------------
__device__ __forceinline__ uint32_t smem_u32(const void* p) {
    uint32_t a;
    asm("{ .reg .u64 t; cvta.to.shared.u64 t, %1; cvt.u32.u64 %0, t; }"
        : "=r"(a) : "l"(p));
    return a;
}

__device__ __forceinline__ void ldsm_x4(uint32_t r[4], uint32_t addr) {
    asm volatile("ldmatrix.sync.aligned.m8n8.x4.shared.b16 {%0,%1,%2,%3}, [%4];"
        : "=r"(r[0]), "=r"(r[1]), "=r"(r[2]), "=r"(r[3]) : "r"(addr));
}

__device__ __forceinline__ void mma16(float d[4], const uint32_t a[4], const uint32_t b[2]) {
    asm volatile(
        "mma.sync.aligned.m16n8k16.row.col.f32.f16.f16.f32 "
        "{%0,%1,%2,%3}, {%4,%5,%6,%7}, {%8,%9}, {%0,%1,%2,%3};"
        : "+f"(d[0]), "+f"(d[1]), "+f"(d[2]), "+f"(d[3])
        : "r"(a[0]), "r"(a[1]), "r"(a[2]), "r"(a[3]), "r"(b[0]), "r"(b[1]));
}

#define CP16(dst, src) \
    asm volatile("cp.async.cg.shared.global [%0], [%1], 16;" :: "r"(dst), "l"(src))
#define CP_COMMIT() asm volatile("cp.async.commit_group;")
template<int N> __device__ __forceinline__ void cp_wait() {
    asm volatile("cp.async.wait_group %0;" :: "n"(N));
}

__device__ __forceinline__ void pair_of(int p, int& f1, int& f2) {
    int a = 0, rem = p;
    while (rem >= FF - a) { rem -= FF - a; a++; }
    f1 = a; f2 = a + rem;
}

// 64 rows x 128B swizzled tile (for gram kernel)
__device__ __forceinline__ int swz_off(int r, int cc) {
    return r * 128 + 16 * (cc ^ (r & 7));
}
// packed BK=32 tile: 2 logical rows per 128B physical row; (row, 16B-col 0..3)
__device__ __forceinline__ int swz2(int m, int kc) {
    return (m >> 1) * 128 + 16 * ((((m & 1) * 4) + kc) ^ ((m >> 1) & 7));
}

// ---------------- K0: Gram via tensor cores, fused embedding gather -----------
// Per batch b: gather E = femb[idx]*val (64x64, rows>=50 zero) into SMEM and
// g_emb; C = E @ E^T; pack upper triangle into g_gram. 2 batches/CTA.
__global__ __launch_bounds__(256)
void gram_mma_kernel(const int* __restrict__ fidx,
                     const float* __restrict__ fval,
                     const float* __restrict__ femb) {
    __shared__ __align__(16) char sm[2 * 8192 + 2 * 64 * 72 * 2];
    const int tid = threadIdx.x;
    const int hb_id = tid >> 7;
    const int t = tid & 127;
    const int w4 = (tid >> 5) & 3;
    const int l = tid & 31;
    const size_t b = (size_t)blockIdx.x * 2 + hb_id;

    char* E = sm + hb_id * 8192;
    __half* Cb = (__half*)(sm + 16384) + hb_id * 64 * 72;

    // fused gather: row = t>>1 (0..63), half hb = t&1 (32 halfs)
    {
        int row = t >> 1, hb = t & 1;
        if (row < FF) {
            int i = fidx[b * FF + row];
            float v = fval[b * FF + row];
            const float4* src = (const float4*)(femb + (size_t)i * EE + hb * 32);
            __half* gout = g_emb + b * FE + (size_t)row * EE + hb * 32;
            #pragma unroll
            for (int j = 0; j < 4; j++) {
                float4 f0 = src[j * 2], f1 = src[j * 2 + 1];
                __half2 h[4];
                h[0] = __floats2half2_rn(f0.x * v, f0.y * v);
                h[1] = __floats2half2_rn(f0.z * v, f0.w * v);
                h[2] = __floats2half2_rn(f1.x * v, f1.y * v);
                h[3] = __floats2half2_rn(f1.z * v, f1.w * v);
                uint4 u = *(uint4*)h;
                *(uint4*)(E + swz_off(row, hb * 4 + j)) = u;
                *(uint4*)(gout + j * 8) = u;
            }
        } else {
            #pragma unroll
            for (int j = 0; j < 4; j++)
                *(uint4*)(E + swz_off(row, hb * 4 + j)) = make_uint4(0, 0, 0, 0);
        }
    }
    __syncthreads();

    const uint32_t Eb = smem_u32(E);
    const int mat = l >> 3, rowin = l & 7;

    uint32_t aoff[4];
    {
        int m = w4 * 16 + (mat & 1) * 8 + rowin;
        #pragma unroll
        for (int ks = 0; ks < 4; ks++)
            aoff[ks] = Eb + swz_off(m, ks * 2 + (mat >> 1));
    }
    uint32_t bfr[8][8];
    #pragma unroll
    for (int nj = 0; nj < 8; nj++) {
        int n = nj * 8 + rowin;
        #pragma unroll
        for (int kk = 0; kk < 2; kk++)
            ldsm_x4(&bfr[nj][kk * 4], Eb + swz_off(n, kk * 4 + mat));
    }

    float acc[8][4];
    #pragma unroll
    for (int nj = 0; nj < 8; nj++)
        #pragma unroll
        for (int q = 0; q < 4; q++) acc[nj][q] = 0.f;

    #pragma unroll
    for (int ks = 0; ks < 4; ks++) {
        uint32_t af[4];
        ldsm_x4(af, aoff[ks]);
        #pragma unroll
        for (int nj = 0; nj < 8; nj++)
            mma16(acc[nj], af, &bfr[nj][ks * 2]);
    }

    {
        int r = w4 * 16 + (l >> 2);
        int c = (l & 3) * 2;
        #pragma unroll
        for (int nj = 0; nj < 8; nj++) {
            int cc = c + nj * 8;
            Cb[r * 72 + cc]           = __float2half(acc[nj][0]);
            Cb[r * 72 + cc + 1]       = __float2half(acc[nj][1]);
            Cb[(r + 8) * 72 + cc]     = __float2half(acc[nj][2]);
            Cb[(r + 8) * 72 + cc + 1] = __float2half(acc[nj][3]);
        }
    }
    __syncthreads();

    __half* dst = g_gram + b * KPAD;
    int base = 0;
    for (int f1 = 0; f1 < FF; f1++) {
        int cnt = FF - f1;
        if (t < cnt) dst[base + t] = Cb[f1 * 72 + f1 + t];
        base += cnt;
    }
    if (t < KPAD - NPAIR) dst[NPAIR + t] = __float2half(0.f);
}

// ---------------- K3: R[d,p] ---------------------------------------------------
__global__ void rk_kernel(const float* __restrict__ q) {
    int d = blockIdx.x;
    const float* qd = q + d * FF;
    __half* dst = g_R + (size_t)d * KPAD;
    for (int p = threadIdx.x; p < KPAD; p += 256) {
        float v = 0.f;
        if (p < NPAIR) {
            int f1, f2; pair_of(p, f1, f2);
            v = qd[f1] * qd[f2] * ((f1 == f2) ? 1.f : 2.f);
        }
        dst[p] = __float2half(v);
    }
}

// ---------------- K4: half copy of product_linear -------------------------------
__global__ void plcopy_kernel(const float* __restrict__ pl) {
    size_t i = (size_t)blockIdx.x * 1024 + threadIdx.x;
    if (i < (size_t)DD * FE) g_PL[i] = __float2half(pl[i]);
}

// ---------------- K5: weight transpose to K-major half --------------------------
__global__ void transpose_kernel(const float* __restrict__ W, __half* __restrict__ Wt,
                                 int R, int Cc) {
    __shared__ float tile[32][33];
    int c0 = blockIdx.x * 32, r0 = blockIdx.y * 32;
    int x = threadIdx.x, y = threadIdx.y;      // 32 x 8
    #pragma unroll
    for (int i = 0; i < 32; i += 8)
        tile[y + i][x] = W[(size_t)(r0 + y + i) * Cc + c0 + x];
    __syncthreads();
    #pragma unroll
    for (int i = 0; i < 32; i += 8)
        Wt[(size_t)(c0 + y + i) * R + r0 + x] = __float2half(tile[x][y + i]);
}

// ---------------- fp16 HMMA GEMM: CTA 128x128, 4 warps 64x64, cp.async x3 ------
// C(16384 x Ntot) = A(16384 x K) @ B(Ntot x K)^T, half K-major operands.
// EPI 0: fp32 store. EPI 1: half relu(lz+sqrt(max(acc,0))+pbias).
// EPI 2: half acc+bias + per-Mtile column partial sum/sumsq.
#define STAGE_BYTES 16384
template<int EPI>
__global__ __launch_bounds__(128, 2)
void hgemm(const __half* __restrict__ A, const __half* __restrict__ B,
           void* __restrict__ Cv, int Ntot, int K,
           const float* __restrict__ bias,
           const float* __restrict__ lzp, const float* __restrict__ pbias,
           float* __restrict__ statS, float* __restrict__ statQ) {
    extern __shared__ char smem[];   // 3 stages x [A 8K][B 8K]
    const uint32_t sb = smem_u32(smem);
    const int tid = threadIdx.x;
    const int l = tid & 31, w = tid >> 5;
    const int wm = w >> 1, wn = w & 1;
    const int m0 = blockIdx.y * 128, n0 = blockIdx.x * 128;
    const int NC = K >> 5;

    // staging: thread t -> row t of A and row t of B, 4 x 16B each
    int aoffS[4], boffS[4];
    #pragma unroll
    for (int j = 0; j < 4; j++) {
        aoffS[j] = swz2(tid, j);
        boffS[j] = 8192 + swz2(tid, j);
    }
    const __half* Ap = A + (size_t)(m0 + tid) * K;
    const __half* Bp = B + (size_t)(n0 + tid) * K;

    // ldmatrix maps
    const int mat = l >> 3, rowin = l & 7;
    uint32_t aoff[4][2], boff[8];
    #pragma unroll
    for (int mi = 0; mi < 4; mi++) {
        int m = wm * 64 + mi * 16 + (mat & 1) * 8 + rowin;
        #pragma unroll
        for (int ks = 0; ks < 2; ks++)
            aoff[mi][ks] = swz2(m, ks * 2 + (mat >> 1));
    }
    #pragma unroll
    for (int nj = 0; nj < 8; nj++) {
        int n = wn * 64 + nj * 8 + rowin;
        boff[nj] = 8192 + swz2(n, mat);
    }

    float acc[4][8][4];
    #pragma unroll
    for (int mi = 0; mi < 4; mi++)
        #pragma unroll
        for (int nj = 0; nj < 8; nj++)
            #pragma unroll
            for (int q = 0; q < 4; q++) acc[mi][nj][q] = 0.f;

    // prologue: stages 0, 1
    #pragma unroll
    for (int s = 0; s < 2; s++) {
        uint32_t base = sb + s * STAGE_BYTES;
        int kb = s * 32;
        #pragma unroll
        for (int j = 0; j < 4; j++) CP16(base + aoffS[j], Ap + kb + j * 8);
        #pragma unroll
        for (int j = 0; j < 4; j++) CP16(base + boffS[j], Bp + kb + j * 8);
        CP_COMMIT();
    }

    int buf = 0;
    for (int c = 0; c < NC; c++) {
        if (c + 1 < NC) cp_wait<1>(); else cp_wait<0>();
        __syncthreads();
        if (c + 2 < NC) {
            int s = (c + 2) % 3;
            uint32_t base = sb + s * STAGE_BYTES;
            int kb = (c + 2) * 32;
            #pragma unroll
            for (int j = 0; j < 4; j++) CP16(base + aoffS[j], Ap + kb + j * 8);
            #pragma unroll
            for (int j = 0; j < 4; j++) CP16(base + boffS[j], Bp + kb + j * 8);
            CP_COMMIT();
        }
        const uint32_t S = sb + buf * STAGE_BYTES;
        uint32_t bfr[8][4];
        #pragma unroll
        for (int nj = 0; nj < 8; nj++) ldsm_x4(bfr[nj], S + boff[nj]);
        #pragma unroll
        for (int ks = 0; ks < 2; ks++) {
            uint32_t af[4][4];
            #pragma unroll
            for (int mi = 0; mi < 4; mi++) ldsm_x4(af[mi], S + aoff[mi][ks]);
            #pragma unroll
            for (int mi = 0; mi < 4; mi++)
                #pragma unroll
                for (int nj = 0; nj < 8; nj++)
                    mma16(acc[mi][nj], af[mi], &bfr[nj][ks * 2]);
        }
        buf = (buf + 1 == 3) ? 0 : buf + 1;
    }

    // ---- epilogue ----
    float* Cf = (float*)Cv;
    __half* Ch = (__half*)Cv;
    const int r0 = m0 + wm * 64 + (l >> 2);
    const int c0b = n0 + wn * 64 + (l & 3) * 2;
    float sS[8][2] = {}, sQ[8][2] = {};
    #pragma unroll
    for (int mi = 0; mi < 4; mi++) {
        int r = r0 + mi * 16;
        #pragma unroll
        for (int nj = 0; nj < 8; nj++) {
            int cc = c0b + nj * 8;
            float d0 = acc[mi][nj][0], d1 = acc[mi][nj][1];
            float d2 = acc[mi][nj][2], d3 = acc[mi][nj][3];
            if (EPI == 0) {
                *(float2*)(Cf + (size_t)r * Ntot + cc)       = make_float2(d0, d1);
                *(float2*)(Cf + (size_t)(r + 8) * Ntot + cc) = make_float2(d2, d3);
            } else if (EPI == 1) {
                d0 = fmaxf(0.f, lzp[(size_t)r * Ntot + cc]           + sqrtf(fmaxf(d0, 0.f)) + pbias[cc]);
                d1 = fmaxf(0.f, lzp[(size_t)r * Ntot + cc + 1]       + sqrtf(fmaxf(d1, 0.f)) + pbias[cc + 1]);
                d2 = fmaxf(0.f, lzp[(size_t)(r + 8) * Ntot + cc]     + sqrtf(fmaxf(d2, 0.f)) + pbias[cc]);
                d3 = fmaxf(0.f, lzp[(size_t)(r + 8) * Ntot + cc + 1] + sqrtf(fmaxf(d3, 0.f)) + pbias[cc + 1]);
                *(__half2*)(Ch + (size_t)r * Ntot + cc)       = __floats2half2_rn(d0, d1);
                *(__half2*)(Ch + (size_t)(r + 8) * Ntot + cc) = __floats2half2_rn(d2, d3);
            } else {
                float b0v = bias[cc], b1v = bias[cc + 1];
                d0 += b0v; d1 += b1v; d2 += b0v; d3 += b1v;
                sS[nj][0] += d0 + d2;           sS[nj][1] += d1 + d3;
                sQ[nj][0] += d0 * d0 + d2 * d2; sQ[nj][1] += d1 * d1 + d3 * d3;
                *(__half2*)(Ch + (size_t)r * Ntot + cc)       = __floats2half2_rn(d0, d1);
                *(__half2*)(Ch + (size_t)(r + 8) * Ntot + cc) = __floats2half2_rn(d2, d3);
            }
        }
    }
    if (EPI == 2) {
        #pragma unroll
        for (int nj = 0; nj < 8; nj++)
            #pragma unroll
            for (int e = 0; e < 2; e++) {
                #pragma unroll
                for (int off = 4; off < 32; off <<= 1) {
                    sS[nj][e] += __shfl_xor_sync(0xffffffffu, sS[nj][e], off);
                    sQ[nj][e] += __shfl_xor_sync(0xffffffffu, sQ[nj][e], off);
                }
            }
        float* sf = (float*)smem;
        __syncthreads();
        if (l < 4) {
            #pragma unroll
            for (int nj = 0; nj < 8; nj++)
                #pragma unroll
                for (int e = 0; e < 2; e++) {
                    int cl = wn * 64 + nj * 8 + (l & 3) * 2 + e;
                    sf[wm * 128 + cl]       = sS[nj][e];
                    sf[256 + wm * 128 + cl] = sQ[nj][e];
                }
        }
        __syncthreads();
        if (tid < 128) {
            statS[(size_t)blockIdx.y * Ntot + n0 + tid] = sf[tid] + sf[128 + tid];
            statQ[(size_t)blockIdx.y * Ntot + n0 + tid] = sf[256 + tid] + sf[384 + tid];
        }
    }
}

// ---------------- BN finalize ----------------------------------------------
__global__ void bnfin_kernel(const float* __restrict__ pS,
                             const float* __restrict__ pQ, int H,
                             const float* __restrict__ scale,
                             const float* __restrict__ offset,
                             float* __restrict__ oA, float* __restrict__ oB) {
    int c = blockIdx.x * blockDim.x + threadIdx.x;
    if (c >= H) return;
    float s = 0.f, q = 0.f;
    for (int t = 0; t < 128; t++) { s += pS[t * H + c]; q += pQ[t * H + c]; }
    float m = s * (1.f / (float)BATCH);
    float v = q * (1.f / (float)BATCH) - m * m;
    float a = scale[0] * rsqrtf(fmaxf(v, 0.f) + 1e-10f);
    oA[c] = a;
    oB[c] = offset[0] - m * a;
}

// ---------------- BN transform of y1 (in place) -----------------------------
__global__ void bntrans_kernel() {
    size_t i = ((size_t)blockIdx.x * 256 + threadIdx.x) * 8;
    int col = (int)(i & (HH1 - 1));
    uint4 u = *(uint4*)(g_y1h + i);
    __half2* h = (__half2*)&u;
    #pragma unroll
    for (int j = 0; j < 4; j++) {
        float x = __low2float(h[j]), y = __high2float(h[j]);
        x = fmaxf(0.f, fmaf(x, g_bnA1[col + 2 * j], g_bnB1[col + 2 * j]));
        y = fmaxf(0.f, fmaf(y, g_bnA1[col + 2 * j + 1], g_bnB1[col + 2 * j + 1]));
        h[j] = __floats2half2_rn(x, y);
    }
    *(uint4*)(g_y1h + i) = u;
}

// ---------------- output head ----------------------------------------------
__global__ void out_kernel(const float* __restrict__ w,
                           const float* __restrict__ ob,
                           float* __restrict__ out) {
    int b = blockIdx.x;
    int tid = threadIdx.x;   // 128 threads
    const __half* row = g_y2h + (size_t)b * HH2;
    float s = 0.f;
    #pragma unroll
    for (int n = tid; n < HH2; n += 128) {
        float v = fmaxf(0.f, fmaf(__half2float(row[n]), g_bnA2[n], g_bnB2[n]));
        s += v * w[n];
    }
    __shared__ float red[128];
    red[tid] = s;
    __syncthreads();
    for (int off = 64; off > 0; off >>= 1) {
        if (tid < off) red[tid] += red[tid + off];
        __syncthreads();
    }
    if (tid == 0) {
        float x = red[0] + ob[0];
        out[b] = 1.f / (1.f + expf(-x));
    }
}

// ---------------- launch ----------------------------------------------------
extern "C" void kernel_launch(void* const* d_in, const int* in_sizes, int n_in,
                              void* d_out, int out_size) {
    const int*   fidx  = (const int*)  d_in[0];
    const float* fval  = (const float*)d_in[1];
    const float* femb  = (const float*)d_in[2];
    const float* pl    = (const float*)d_in[3];
    const float* pbias = (const float*)d_in[4];
    const float* pq    = (const float*)d_in[5];
    const float* W0    = (const float*)d_in[6];
    const float* b0    = (const float*)d_in[7];
    const float* W1    = (const float*)d_in[8];
    const float* b1    = (const float*)d_in[9];
    const float* bnS   = (const float*)d_in[10];
    const float* bnO   = (const float*)d_in[11];
    const float* ow    = (const float*)d_in[12];
    const float* ob    = (const float*)d_in[13];
    float* out = (float*)d_out;

    void *emb, *gram, *PL, *R, *W0t, *W1t, *y0h, *y1h, *y2h, *lz, *pS, *pQ;
    void *A1, *B1, *A2, *B2;
    cudaGetSymbolAddress(&emb,  g_emb);
    cudaGetSymbolAddress(&gram, g_gram);
    cudaGetSymbolAddress(&PL,   g_PL);
    cudaGetSymbolAddress(&R,    g_R);
    cudaGetSymbolAddress(&W0t,  g_W0t);
    cudaGetSymbolAddress(&W1t,  g_W1t);
    cudaGetSymbolAddress(&y0h,  g_y0h);
    cudaGetSymbolAddress(&y1h,  g_y1h);
    cudaGetSymbolAddress(&y2h,  g_y2h);
    cudaGetSymbolAddress(&lz,   g_lz);
    cudaGetSymbolAddress(&pS,   g_pS);
    cudaGetSymbolAddress(&pQ,   g_pQ);
    cudaGetSymbolAddress(&A1,   g_bnA1);
    cudaGetSymbolAddress(&B1,   g_bnB1);
    cudaGetSymbolAddress(&A2,   g_bnA2);
    cudaGetSymbolAddress(&B2,   g_bnB2);

    const int SMEM = 3 * STAGE_BYTES;   // 48 KB
    cudaFuncSetAttribute(hgemm<0>, cudaFuncAttributeMaxDynamicSharedMemorySize, SMEM);
    cudaFuncSetAttribute(hgemm<1>, cudaFuncAttributeMaxDynamicSharedMemorySize, SMEM);
    cudaFuncSetAttribute(hgemm<2>, cudaFuncAttributeMaxDynamicSharedMemorySize, SMEM);

    gram_mma_kernel<<<BATCH / 2, 256>>>(fidx, fval, femb);                       // 0
    plcopy_kernel<<<(DD * FE + 1023) / 1024, 1024>>>(pl);                        // 1
    rk_kernel<<<DD, 256>>>(pq);                                                   // 2
    // 3: LZ = emb @ PL^T  (N=512, K=3200)  <-- profiled launch
    hgemm<0><<<dim3(4, 128), 128, SMEM>>>(
        (const __half*)emb, (const __half*)PL, lz, DD, FE,
        nullptr, nullptr, nullptr, nullptr, nullptr);
    // y0 = relu(lz + sqrt(G @ R^T) + pbias)
    hgemm<1><<<dim3(4, 128), 128, SMEM>>>(
        (const __half*)gram, (const __half*)R, y0h, DD, KPAD,
        nullptr, (const float*)lz, pbias, nullptr, nullptr);
    transpose_kernel<<<dim3(HH1 / 32, DD / 32), dim3(32, 8)>>>(W0, (__half*)W0t, DD, HH1);
    // y1 = y0 @ W0 + b0, with BN partials
    hgemm<2><<<dim3(8, 128), 128, SMEM>>>(
        (const __half*)y0h, (const __half*)W0t, y1h, HH1, DD,
        b0, nullptr, nullptr, (float*)pS, (float*)pQ);
    bnfin_kernel<<<HH1 / 256, 256>>>((const float*)pS, (const float*)pQ, HH1,
                                     bnS, bnO, (float*)A1, (float*)B1);
    bntrans_kernel<<<BATCH * HH1 / (256 * 8), 256>>>();
    transpose_kernel<<<dim3(HH2 / 32, HH1 / 32), dim3(32, 8)>>>(W1, (__half*)W1t, HH1, HH2);
    // y2 = bnrelu(y1) @ W1 + b1, with BN partials
    hgemm<2><<<dim3(4, 128), 128, SMEM>>>(
        (const __half*)y1h, (const __half*)W1t, y2h, HH2, HH1,
        b1, nullptr, nullptr, (float*)pS, (float*)pQ);
    bnfin_kernel<<<HH2 / 256, 256>>>((const float*)pS, (const float*)pQ, HH2,
                                     bnS, bnO, (float*)A2, (float*)B2);
    out_kernel<<<BATCH, 128>>>(ow, ob, out);
}